// round 13
// baseline (speedup 1.0000x reference)
#include <cuda_runtime.h>
#include <cuda_bf16.h>
#include <cstdint>
#include <cstddef>

// Problem constants
#define BB 32
#define LL 512
#define HH 1024
#define HID 512
#define G4 2048   // 4*HID
#define TWOH 2048 // 2*H

// ---------------------------------------------------------------------------
// Scratch (static __device__ arrays)
// ---------------------------------------------------------------------------
__device__ __align__(16) float d_S[(size_t)BB * LL * LL];
__device__ __align__(16) float d_Gf[(size_t)LL * BB * G4];
__device__ __align__(16) float d_Gb[(size_t)LL * BB * G4];
__device__ unsigned d_bar[2];
// h ping-pong in split bf16
__device__ __align__(16) __nv_bfloat16 d_hbf_hi[2][2][BB * HID];
__device__ __align__(16) __nv_bfloat16 d_hbf_lo[2][2][BB * HID];
// bf16 split operands
__device__ __align__(16) __nv_bfloat16 d_xhi[(size_t)BB * LL * HH];
__device__ __align__(16) __nv_bfloat16 d_xlo[(size_t)BB * LL * HH];
__device__ __align__(16) __nv_bfloat16 d_xThi[(size_t)BB * HH * LL];
__device__ __align__(16) __nv_bfloat16 d_xTlo[(size_t)BB * HH * LL];
__device__ __align__(16) __nv_bfloat16 d_Shi[(size_t)BB * LL * LL];
__device__ __align__(16) __nv_bfloat16 d_Slo[(size_t)BB * LL * LL];
__device__ __align__(16) __nv_bfloat16 d_NXhi[(size_t)BB * LL * TWOH];
__device__ __align__(16) __nv_bfloat16 d_NXlo[(size_t)BB * LL * TWOH];
__device__ __align__(16) __nv_bfloat16 d_Whi[2][(size_t)G4 * TWOH];
__device__ __align__(16) __nv_bfloat16 d_Wlo[2][(size_t)G4 * TWOH];

// ---------------------------------------------------------------------------
// PTX helpers — base sm_100-safe (cp.async / ldmatrix / mma.sync)
// ---------------------------------------------------------------------------
__device__ __forceinline__ uint32_t smem_u32(const void* p) {
    uint32_t a;
    asm("{ .reg .u64 t; cvta.to.shared.u64 t, %1; cvt.u32.u64 %0, t; }" : "=r"(a) : "l"(p));
    return a;
}
__device__ __forceinline__ void cp_async16(uint32_t dst, const void* src) {
    asm volatile("cp.async.cg.shared.global [%0], [%1], 16;" :: "r"(dst), "l"(src));
}
#define CP_COMMIT() asm volatile("cp.async.commit_group;" ::: "memory")
#define CP_WAIT1()  asm volatile("cp.async.wait_group 1;" ::: "memory")
#define CP_WAIT0()  asm volatile("cp.async.wait_group 0;" ::: "memory")

__device__ __forceinline__ void ldm_x4(uint32_t* r, uint32_t a) {
    asm volatile("ldmatrix.sync.aligned.m8n8.x4.shared.b16 {%0,%1,%2,%3}, [%4];"
                 : "=r"(r[0]), "=r"(r[1]), "=r"(r[2]), "=r"(r[3]) : "r"(a));
}
__device__ __forceinline__ void mma_bf16(float* d, const uint32_t* a, const uint32_t* b) {
    asm volatile("mma.sync.aligned.m16n8k16.row.col.f32.bf16.bf16.f32 "
                 "{%0,%1,%2,%3}, {%4,%5,%6,%7}, {%8,%9}, {%0,%1,%2,%3};"
                 : "+f"(d[0]), "+f"(d[1]), "+f"(d[2]), "+f"(d[3])
                 : "r"(a[0]), "r"(a[1]), "r"(a[2]), "r"(a[3]), "r"(b[0]), "r"(b[1]));
}

#define SWZ128(off) ((off) ^ (((off) >> 3) & 0x70))

// ---------------------------------------------------------------------------
// init: zero split-h buffers + barrier counters
// ---------------------------------------------------------------------------
__global__ void init_state() {
    int i = blockIdx.x * blockDim.x + threadIdx.x;
    if (i < 2 * 2 * BB * HID) {
        ((__nv_bfloat16*)d_hbf_hi)[i] = __float2bfloat16(0.f);
        ((__nv_bfloat16*)d_hbf_lo)[i] = __float2bfloat16(0.f);
    }
    if (i < 2) d_bar[i] = 0u;
}

// ---------------------------------------------------------------------------
// Splits
// ---------------------------------------------------------------------------
__device__ __forceinline__ void split4(float4 v, __nv_bfloat162& H0, __nv_bfloat162& H1,
                                       __nv_bfloat162& L0, __nv_bfloat162& L1) {
    __nv_bfloat16 h0 = __float2bfloat16(v.x), h1 = __float2bfloat16(v.y);
    __nv_bfloat16 h2 = __float2bfloat16(v.z), h3 = __float2bfloat16(v.w);
    H0 = {h0, h1}; H1 = {h2, h3};
    L0 = {__float2bfloat16(v.x - __bfloat162float(h0)),
          __float2bfloat16(v.y - __bfloat162float(h1))};
    L1 = {__float2bfloat16(v.z - __bfloat162float(h2)),
          __float2bfloat16(v.w - __bfloat162float(h3))};
}

__global__ void __launch_bounds__(256) split_bf16(
    const float* __restrict__ src, __nv_bfloat16* __restrict__ hi,
    __nv_bfloat16* __restrict__ lo, size_t n4)
{
    size_t i = (size_t)blockIdx.x * 256 + threadIdx.x;
    if (i >= n4) return;
    __nv_bfloat162 H0, H1, L0, L1;
    split4(((const float4*)src)[i], H0, H1, L0, L1);
    ((__nv_bfloat162*)hi)[i * 2]     = H0;
    ((__nv_bfloat162*)hi)[i * 2 + 1] = H1;
    ((__nv_bfloat162*)lo)[i * 2]     = L0;
    ((__nv_bfloat162*)lo)[i * 2 + 1] = L1;
}

__global__ void __launch_bounds__(256) split_x(
    const float* __restrict__ x,
    __nv_bfloat16* __restrict__ xhi, __nv_bfloat16* __restrict__ xlo,
    __nv_bfloat16* __restrict__ NXhi, __nv_bfloat16* __restrict__ NXlo)
{
    size_t i = (size_t)blockIdx.x * 256 + threadIdx.x;
    if (i >= (size_t)BB * LL * HH / 4) return;
    __nv_bfloat162 H0, H1, L0, L1;
    split4(((const float4*)x)[i], H0, H1, L0, L1);
    ((__nv_bfloat162*)xhi)[i * 2]     = H0;
    ((__nv_bfloat162*)xhi)[i * 2 + 1] = H1;
    ((__nv_bfloat162*)xlo)[i * 2]     = L0;
    ((__nv_bfloat162*)xlo)[i * 2 + 1] = L1;
    size_t bl = i >> 8, d4 = i & 255;
    size_t o = bl * 1024 + 512 + d4 * 2;
    ((__nv_bfloat162*)NXhi)[o]     = H0;
    ((__nv_bfloat162*)NXhi)[o + 1] = H1;
    ((__nv_bfloat162*)NXlo)[o]     = L0;
    ((__nv_bfloat162*)NXlo)[o + 1] = L1;
}

__global__ void transpose_x(
    const __nv_bfloat16* __restrict__ hi, const __nv_bfloat16* __restrict__ lo,
    __nv_bfloat16* __restrict__ Thi, __nv_bfloat16* __restrict__ Tlo)
{
    __shared__ __nv_bfloat16 th[32][33], tl[32][33];
    const int b = blockIdx.z;
    const int d0 = blockIdx.x * 32, l0 = blockIdx.y * 32;
    const int tx = threadIdx.x, ty = threadIdx.y;
    const size_t si = (size_t)b * LL * HH;
    #pragma unroll
    for (int i = 0; i < 4; i++) {
        int l = ty + i * 8;
        th[l][tx] = hi[si + (size_t)(l0 + l) * HH + d0 + tx];
        tl[l][tx] = lo[si + (size_t)(l0 + l) * HH + d0 + tx];
    }
    __syncthreads();
    const size_t so = (size_t)b * HH * LL;
    #pragma unroll
    for (int i = 0; i < 4; i++) {
        int d = ty + i * 8;
        Thi[so + (size_t)(d0 + d) * LL + l0 + tx] = th[tx][d];
        Tlo[so + (size_t)(d0 + d) * LL + l0 + tx] = tl[tx][d];
    }
}

// ---------------------------------------------------------------------------
// Unified bf16-split tensor GEMM. Tile 128(M) x 64(N), 8 warps in 4x2,
// warp tile 32x32, KC=64, 2-stage cp.async, 2 CTAs/SM.
// EPI=0: fp32 C batched; EPI=1: split-bf16 NX rows (ld TWOH);
// EPI=2: time-major gates + bias.
// ---------------------------------------------------------------------------
#define KC 64
#define TILEA 16384              // 128 rows x 128B
#define TILEBB 8192              // 64 rows x 128B
#define STAGEB (2 * TILEA + 2 * TILEBB)   // Ahi Alo Bhi Blo = 48KB
#define T3_DSMEM (1024 + 2 * STAGEB)      // ~97KB

template <int EPI>
__global__ void __launch_bounds__(256, 2) gemm_t3(
    const __nv_bfloat16* __restrict__ Ahi, const __nv_bfloat16* __restrict__ Alo,
    const __nv_bfloat16* __restrict__ Bhi, const __nv_bfloat16* __restrict__ Blo,
    int K, int lda, int ldb, size_t sA, size_t sB,
    float* __restrict__ Cf, int ldc, size_t sC,
    __nv_bfloat16* __restrict__ Chi, __nv_bfloat16* __restrict__ Clo,
    const float* __restrict__ bias1, const float* __restrict__ bias2)
{
    extern __shared__ char dsm[];
    char* basep = (char*)(((uintptr_t)dsm + 1023) & ~(uintptr_t)1023);
    const uint32_t sbase = smem_u32(basep);

    const int tid = threadIdx.x;
    const int wid = tid >> 5, lane = tid & 31;
    const int warp_m = wid >> 1, warp_n = wid & 1;   // 4 x 2, warp tile 32x32
    const int m0 = blockIdx.y * 128, n0 = blockIdx.x * 64;
    const int z = blockIdx.z;
    Ahi += (size_t)z * sA; Alo += (size_t)z * sA;
    Bhi += (size_t)z * sB; Blo += (size_t)z * sB;

    float acc[2][4][4] = {};
    const int nchunk = K / KC;

    auto issue = [&](int chunk) {
        const uint32_t st = sbase + (chunk & 1) * STAGEB;
        const int kc = chunk * KC;
        #pragma unroll
        for (int i = 0; i < 4; i++) {
            int u = tid + i * 256;               // A: 1024 16B units
            int r = u >> 3, cu = u & 7;
            uint32_t sw = SWZ128((uint32_t)(r * 128 + cu * 16));
            size_t ao = (size_t)(m0 + r) * lda + kc + cu * 8;
            cp_async16(st + sw,         Ahi + ao);
            cp_async16(st + TILEA + sw, Alo + ao);
        }
        #pragma unroll
        for (int i = 0; i < 2; i++) {
            int u = tid + i * 256;               // B: 512 16B units
            int r = u >> 3, cu = u & 7;
            uint32_t sw = SWZ128((uint32_t)(r * 128 + cu * 16));
            size_t bo = (size_t)(n0 + r) * ldb + kc + cu * 8;
            cp_async16(st + 2 * TILEA + sw,          Bhi + bo);
            cp_async16(st + 2 * TILEA + TILEBB + sw, Blo + bo);
        }
    };

    issue(0); CP_COMMIT();

    for (int c = 0; c < nchunk; c++) {
        if (c + 1 < nchunk) issue(c + 1);
        CP_COMMIT();
        CP_WAIT1();
        __syncthreads();
        const uint32_t st = sbase + (c & 1) * STAGEB;

        #pragma unroll
        for (int ks = 0; ks < 4; ks++) {
            const int kb = ks * 32;
            uint32_t ah[2][4], al[2][4], bh[4][2], bl2[4][2];
            #pragma unroll
            for (int mt = 0; mt < 2; mt++) {
                int row = warp_m * 32 + mt * 16 + (lane & 15);
                uint32_t off = SWZ128((uint32_t)(row * 128 + kb + ((lane >> 4) * 16)));
                ldm_x4(ah[mt], st + off);
                ldm_x4(al[mt], st + TILEA + off);
            }
            #pragma unroll
            for (int ntp = 0; ntp < 2; ntp++) {
                int row = warp_n * 32 + ntp * 16 + ((lane >> 4) * 8) + (lane & 7);
                uint32_t off = SWZ128((uint32_t)(row * 128 + kb + (((lane >> 3) & 1) * 16)));
                uint32_t r4[4];
                ldm_x4(r4, st + 2 * TILEA + off);
                bh[2 * ntp][0] = r4[0]; bh[2 * ntp][1] = r4[1];
                bh[2 * ntp + 1][0] = r4[2]; bh[2 * ntp + 1][1] = r4[3];
                ldm_x4(r4, st + 2 * TILEA + TILEBB + off);
                bl2[2 * ntp][0] = r4[0]; bl2[2 * ntp][1] = r4[1];
                bl2[2 * ntp + 1][0] = r4[2]; bl2[2 * ntp + 1][1] = r4[3];
            }
            #pragma unroll
            for (int mt = 0; mt < 2; mt++)
                #pragma unroll
                for (int nt = 0; nt < 4; nt++) {
                    mma_bf16(acc[mt][nt], ah[mt], bh[nt]);
                    mma_bf16(acc[mt][nt], ah[mt], bl2[nt]);
                    mma_bf16(acc[mt][nt], al[mt], bh[nt]);
                }
        }
        __syncthreads();
    }

    // Epilogue
    const int g = lane >> 2, tc = lane & 3;
    #pragma unroll
    for (int nt = 0; nt < 4; nt++) {
        int col = n0 + warp_n * 32 + nt * 8 + tc * 2;
        float b0v = 0.f, b1v = 0.f;
        if (EPI == 2) {
            b0v = bias1[col] + bias2[col];
            b1v = bias1[col + 1] + bias2[col + 1];
        }
        #pragma unroll
        for (int mt = 0; mt < 2; mt++) {
            #pragma unroll
            for (int half = 0; half < 2; half++) {
                int ml = warp_m * 32 + mt * 16 + g + half * 8;
                float v0 = acc[mt][nt][half * 2] + b0v;
                float v1 = acc[mt][nt][half * 2 + 1] + b1v;
                if (EPI == 0) {
                    *(float2*)(Cf + (size_t)z * sC + (size_t)(m0 + ml) * ldc + col)
                        = make_float2(v0, v1);
                } else if (EPI == 1) {
                    size_t row = (size_t)z * LL + m0 + ml;
                    __nv_bfloat16 h0 = __float2bfloat16(v0), h1 = __float2bfloat16(v1);
                    __nv_bfloat162 hv = {h0, h1};
                    __nv_bfloat162 lv = {__float2bfloat16(v0 - __bfloat162float(h0)),
                                         __float2bfloat16(v1 - __bfloat162float(h1))};
                    *(__nv_bfloat162*)(Chi + row * TWOH + col) = hv;
                    *(__nv_bfloat162*)(Clo + row * TWOH + col) = lv;
                } else {
                    int m = m0 + ml;
                    int t = m & 511, b = m >> 9;
                    *(float2*)(Cf + ((size_t)t * 32 + b) * 2048 + col)
                        = make_float2(v0, v1);
                }
            }
        }
    }
}

// ---------------------------------------------------------------------------
// Masked softmax over last axis (512) with fused split-bf16 output.
// ---------------------------------------------------------------------------
__global__ void __launch_bounds__(256) softmax512(const float* __restrict__ S,
                                                  const float* __restrict__ mask,
                                                  __nv_bfloat16* __restrict__ Ohi,
                                                  __nv_bfloat16* __restrict__ Olo)
{
    const int l = blockIdx.x, b = blockIdx.y;
    const float* row = S + ((size_t)b * LL + l) * LL;
    const float* m = mask + (size_t)b * LL;
    const int tid = threadIdx.x;

    float m0 = m[tid], m1 = m[tid + 256];
    float v0 = (m0 > 0.5f) ? row[tid]       : -1e20f;
    float v1 = (m1 > 0.5f) ? row[tid + 256] : -1e20f;

    __shared__ float red[8];
    float mx = fmaxf(v0, v1);
    #pragma unroll
    for (int o = 16; o > 0; o >>= 1) mx = fmaxf(mx, __shfl_xor_sync(0xffffffffu, mx, o));
    if ((tid & 31) == 0) red[tid >> 5] = mx;
    __syncthreads();
    float bm = red[0];
    #pragma unroll
    for (int i = 1; i < 8; i++) bm = fmaxf(bm, red[i]);

    float e0 = expf(v0 - bm);
    float e1 = expf(v1 - bm);
    float sum = e0 + e1;
    #pragma unroll
    for (int o = 16; o > 0; o >>= 1) sum += __shfl_xor_sync(0xffffffffu, sum, o);
    __syncthreads();
    if ((tid & 31) == 0) red[tid >> 5] = sum;
    __syncthreads();
    float bs = 0.f;
    #pragma unroll
    for (int i = 0; i < 8; i++) bs += red[i];

    float inv = 1.0f / bs;
    float p0 = e0 * inv, p1 = e1 * inv;
    size_t o = ((size_t)b * LL + l) * LL;
    __nv_bfloat16 h0 = __float2bfloat16(p0);
    __nv_bfloat16 h1 = __float2bfloat16(p1);
    Ohi[o + tid]       = h0;
    Ohi[o + tid + 256] = h1;
    Olo[o + tid]       = __float2bfloat16(p0 - __bfloat162float(h0));
    Olo[o + tid + 256] = __float2bfloat16(p1 - __bfloat162float(h1));
}

// ---------------------------------------------------------------------------
// Persistent bidirectional LSTM recurrence — TENSOR CORE (unchanged, passing)
// ---------------------------------------------------------------------------
__device__ __forceinline__ float sigm(float x) { return 1.0f / (1.0f + expf(-x)); }

#define LWH 0
#define LWL 32768
#define LHH 65536
#define LHL 98304
#define LSTM_DSMEM 132096

__global__ void __launch_bounds__(256, 1) lstm_rec(
    const float* __restrict__ Whf, const float* __restrict__ Whb,
    const int* __restrict__ x_len, float* __restrict__ out)
{
    extern __shared__ char lsm[];
    char* basep = (char*)(((uintptr_t)lsm + 1023) & ~(uintptr_t)1023);
    const uint32_t sbase = smem_u32(basep);

    __shared__ float gbuf[32][33];
    __shared__ float sG[32][36];
    __shared__ float cbuf[8][32];
    __shared__ float hown[8][32];
    __shared__ int s_len[32];

    const int tid = threadIdx.x;
    const int wid = tid >> 5, lane = tid & 31;
    const int warp_m = wid >> 2, warp_n = wid & 3;
    const int dir = blockIdx.x >> 6;
    const int u0 = (blockIdx.x & 63) * 8;
    const float* __restrict__ G = dir ? d_Gb : d_Gf;
    const float* __restrict__ W = dir ? Whb : Whf;

    if (tid < 32) s_len[tid] = x_len[tid];
    {
        int ul = tid & 7, b = tid >> 3;
        cbuf[ul][b] = 0.f; hown[ul][b] = 0.f;
    }

    {
        int lr = tid >> 3, kg = tid & 7;
        int r = (lr >> 3) * 512 + u0 + (lr & 7);
        const float4* wr = (const float4*)(W + (size_t)r * 512 + kg * 64);
        #pragma unroll
        for (int v = 0; v < 16; v++) {
            __nv_bfloat162 H0, H1, L0, L1;
            split4(wr[v], H0, H1, L0, L1);
            uint32_t off = kg * 4096 + SWZ128((uint32_t)(lr * 128 + v * 8));
            *(__nv_bfloat162*)(basep + LWH + off)     = H0;
            *(__nv_bfloat162*)(basep + LWH + off + 4) = H1;
            *(__nv_bfloat162*)(basep + LWL + off)     = L0;
            *(__nv_bfloat162*)(basep + LWL + off + 4) = L1;
        }
    }
    __syncthreads();

    const uint32_t aRowOff = (uint32_t)((warp_m * 16 + (lane & 15)) * 128 + (lane >> 4) * 16);
    const uint32_t bRowOff = (uint32_t)((warp_n * 8 + (lane & 7)) * 128 + ((lane >> 3) & 1) * 16);
    const uint32_t bTile = (lane < 16) ? (sbase + LWH) : (sbase + LWL);

    for (int s = 0; s < 512; s++) {
        const int t = dir ? (511 - s) : s;
        const int rb = s & 1, wb = rb ^ 1;
        const __nv_bfloat16* hgHi = &d_hbf_hi[dir][rb][0];
        const __nv_bfloat16* hgLo = &d_hbf_lo[dir][rb][0];

        #pragma unroll
        for (int i = 0; i < 8; i++) {
            int u = tid + i * 256;
            int b = u >> 6, ch = (u >> 3) & 7, cu = u & 7;
            uint32_t sw = ch * 4096 + SWZ128((uint32_t)(b * 128 + cu * 16));
            cp_async16(sbase + LHH + sw, hgHi + b * 512 + ch * 64 + cu * 8);
            cp_async16(sbase + LHL + sw, hgLo + b * 512 + ch * 64 + cu * 8);
        }
        CP_COMMIT();
        {
            int pair = tid >> 1, half = tid & 1;
            int b = pair >> 2, gate = pair & 3;
            const float* gsrc = G + ((size_t)t * 32 + b) * 2048 + gate * 512 + u0 + half * 4;
            cp_async16(smem_u32(&sG[b][gate * 8 + half * 4]), gsrc);
        }
        CP_COMMIT();
        CP_WAIT1();
        __syncthreads();

        float acc[4] = {0.f, 0.f, 0.f, 0.f};
        #pragma unroll 8
        for (int kst = 0; kst < 32; kst++) {
            uint32_t kc = (uint32_t)(kst >> 2) * 4096;
            uint32_t kb = (uint32_t)(kst & 3) * 32;
            uint32_t ao = kc + SWZ128(aRowOff + kb);
            uint32_t bo = kc + SWZ128(bRowOff + kb);
            uint32_t ah[4], al[4], bbx[4];
            ldm_x4(ah, sbase + LHH + ao);
            ldm_x4(al, sbase + LHL + ao);
            ldm_x4(bbx, bTile + bo);
            mma_bf16(acc, ah, bbx);
            mma_bf16(acc, ah, bbx + 2);
            mma_bf16(acc, al, bbx);
        }

        {
            int g = lane >> 2, tc = lane & 3;
            int n = warp_n * 8 + tc * 2, m = warp_m * 16 + g;
            gbuf[n][m]         = acc[0];
            gbuf[n + 1][m]     = acc[1];
            gbuf[n][m + 8]     = acc[2];
            gbuf[n + 1][m + 8] = acc[3];
        }
        CP_WAIT0();
        __syncthreads();

        {
            int b = tid >> 3, ul = tid & 7;
            float gi = gbuf[ul][b]      + sG[b][ul];
            float gf = gbuf[8 + ul][b]  + sG[b][8 + ul];
            float gg = gbuf[16 + ul][b] + sG[b][16 + ul];
            float go = gbuf[24 + ul][b] + sG[b][24 + ul];
            float c  = cbuf[ul][b];
            float nc = sigm(gf) * c + sigm(gi) * tanhf(gg);
            float nh = sigm(go) * tanhf(nc);
            bool valid = (t < s_len[b]);
            float hn = valid ? nh : hown[ul][b];
            float cn = valid ? nc : c;
            cbuf[ul][b] = cn;
            hown[ul][b] = hn;
            __nv_bfloat16 hhi = __float2bfloat16(hn);
            __nv_bfloat16 hlo = __float2bfloat16(hn - __bfloat162float(hhi));
            d_hbf_hi[dir][wb][b * 512 + u0 + ul] = hhi;
            d_hbf_lo[dir][wb][b * 512 + u0 + ul] = hlo;
            if (s == 511) out[(size_t)b * 1024 + dir * 512 + u0 + ul] = hn;
        }

        if (s == 511) break;

        __threadfence();
        __syncthreads();
        if (tid == 0) {
            atomicAdd(&d_bar[dir], 1u);
            const unsigned target = 64u * (unsigned)(s + 1);
            while (true) {
                unsigned v;
                asm volatile("ld.global.acquire.gpu.u32 %0, [%1];" : "=r"(v) : "l"(&d_bar[dir]));
                if (v >= target) break;
                __nanosleep(64);
            }
            __threadfence();
        }
        __syncthreads();
    }
}

// ---------------------------------------------------------------------------
// kernel_launch
// ---------------------------------------------------------------------------
extern "C" void kernel_launch(void* const* d_in, const int* in_sizes, int n_in,
                              void* d_out, int out_size)
{
    const float* x    = (const float*)d_in[0];
    const int*   xlen = (const int*)  d_in[1];
    const float* am   = (const float*)d_in[2];
    const float* Wif  = (const float*)d_in[3];
    const float* Whf  = (const float*)d_in[4];
    const float* bif  = (const float*)d_in[5];
    const float* bhf  = (const float*)d_in[6];
    const float* Wib  = (const float*)d_in[7];
    const float* Whb  = (const float*)d_in[8];
    const float* bib  = (const float*)d_in[9];
    const float* bhb  = (const float*)d_in[10];
    float* out = (float*)d_out;

    void *pS, *pGf, *pGb, *pxhi, *pxlo, *pxThi, *pxTlo, *pShi, *pSlo,
         *pNXhi, *pNXlo, *pWhi, *pWlo;
    cudaGetSymbolAddress(&pS,    d_S);
    cudaGetSymbolAddress(&pGf,   d_Gf);
    cudaGetSymbolAddress(&pGb,   d_Gb);
    cudaGetSymbolAddress(&pxhi,  d_xhi);
    cudaGetSymbolAddress(&pxlo,  d_xlo);
    cudaGetSymbolAddress(&pxThi, d_xThi);
    cudaGetSymbolAddress(&pxTlo, d_xTlo);
    cudaGetSymbolAddress(&pShi,  d_Shi);
    cudaGetSymbolAddress(&pSlo,  d_Slo);
    cudaGetSymbolAddress(&pNXhi, d_NXhi);
    cudaGetSymbolAddress(&pNXlo, d_NXlo);
    cudaGetSymbolAddress(&pWhi,  d_Whi);
    cudaGetSymbolAddress(&pWlo,  d_Wlo);
    float* S = (float*)pS;
    float* Gf = (float*)pGf;
    float* Gb = (float*)pGb;
    __nv_bfloat16* xhi  = (__nv_bfloat16*)pxhi;
    __nv_bfloat16* xlo  = (__nv_bfloat16*)pxlo;
    __nv_bfloat16* xThi = (__nv_bfloat16*)pxThi;
    __nv_bfloat16* xTlo = (__nv_bfloat16*)pxTlo;
    __nv_bfloat16* Shi  = (__nv_bfloat16*)pShi;
    __nv_bfloat16* Slo  = (__nv_bfloat16*)pSlo;
    __nv_bfloat16* NXhi = (__nv_bfloat16*)pNXhi;
    __nv_bfloat16* NXlo = (__nv_bfloat16*)pNXlo;
    __nv_bfloat16* Whi0 = (__nv_bfloat16*)pWhi;
    __nv_bfloat16* Whi1 = Whi0 + (size_t)G4 * TWOH;
    __nv_bfloat16* Wlo0 = (__nv_bfloat16*)pWlo;
    __nv_bfloat16* Wlo1 = Wlo0 + (size_t)G4 * TWOH;

    cudaFuncSetAttribute(lstm_rec, cudaFuncAttributeMaxDynamicSharedMemorySize, LSTM_DSMEM);
    cudaFuncSetAttribute(gemm_t3<0>, cudaFuncAttributeMaxDynamicSharedMemorySize, T3_DSMEM);
    cudaFuncSetAttribute(gemm_t3<1>, cudaFuncAttributeMaxDynamicSharedMemorySize, T3_DSMEM);
    cudaFuncSetAttribute(gemm_t3<2>, cudaFuncAttributeMaxDynamicSharedMemorySize, T3_DSMEM);

    init_state<<<256, 256>>>();

    {
        size_t n4 = (size_t)BB * LL * HH / 4;
        split_x<<<(unsigned)((n4 + 255) / 256), 256>>>(x, xhi, xlo, NXhi, NXlo);
    }

    transpose_x<<<dim3(HH / 32, LL / 32, BB), dim3(32, 8)>>>(xhi, xlo, xThi, xTlo);

    // scores: S[b] = x_b * x_b^T  (K=1024)
    gemm_t3<0><<<dim3(LL / 64, LL / 128, BB), 256, T3_DSMEM>>>(
        xhi, xlo, xhi, xlo, HH, HH, HH,
        (size_t)LL * HH, (size_t)LL * HH,
        S, LL, (size_t)LL * LL, nullptr, nullptr, nullptr, nullptr);

    // softmax + fused split-bf16 output
    softmax512<<<dim3(LL, BB), 256>>>(S, am, Shi, Slo);

    // att @ x -> NX[:, :, 0:1024] split-bf16 (K=512, B = x^T)
    gemm_t3<1><<<dim3(HH / 64, LL / 128, BB), 256, T3_DSMEM>>>(
        Shi, Slo, xThi, xTlo, LL, LL, LL,
        (size_t)LL * LL, (size_t)HH * LL,
        nullptr, 0, 0, NXhi, NXlo, nullptr, nullptr);

    {
        size_t w4 = (size_t)G4 * TWOH / 4;
        split_bf16<<<(unsigned)((w4 + 255) / 256), 256>>>(Wif, Whi0, Wlo0, w4);
        split_bf16<<<(unsigned)((w4 + 255) / 256), 256>>>(Wib, Whi1, Wlo1, w4);
    }

    // gate precompute (K=2048), time-major out with bias
    gemm_t3<2><<<dim3(G4 / 64, (BB * LL) / 128, 1), 256, T3_DSMEM>>>(
        NXhi, NXlo, Whi0, Wlo0, TWOH, TWOH, TWOH, 0, 0,
        Gf, 0, 0, nullptr, nullptr, bif, bhf);
    gemm_t3<2><<<dim3(G4 / 64, (BB * LL) / 128, 1), 256, T3_DSMEM>>>(
        NXhi, NXlo, Whi1, Wlo1, TWOH, TWOH, TWOH, 0, 0,
        Gb, 0, 0, nullptr, nullptr, bib, bhb);

    // Persistent bidirectional recurrence (tensor cores)
    lstm_rec<<<128, 256, LSTM_DSMEM>>>(Whf, Whb, xlen, out);
}

// round 14
// speedup vs baseline: 1.0431x; 1.0431x over previous
#include <cuda_runtime.h>
#include <cuda_bf16.h>
#include <cstdint>
#include <cstddef>

// Problem constants
#define BB 32
#define LL 512
#define HH 1024
#define HID 512
#define G4 2048   // 4*HID
#define TWOH 2048 // 2*H

// ---------------------------------------------------------------------------
// Scratch (static __device__ arrays)
// ---------------------------------------------------------------------------
__device__ __align__(16) float d_S[(size_t)BB * LL * LL];        // scores/att fp32
__device__ __align__(16) float d_xT[(size_t)BB * HH * LL];       // x^T per batch
__device__ __align__(16) float d_NX[(size_t)BB * LL * TWOH];     // [att@x, x] fp32
__device__ __align__(16) float d_Gf[(size_t)LL * BB * G4];       // gates fwd [t][b][4H]
__device__ __align__(16) float d_Gb[(size_t)LL * BB * G4];
__device__ unsigned d_bar[2];
// h ping-pong in split bf16 (lstm_rec path, unchanged)
__device__ __align__(16) __nv_bfloat16 d_hbf_hi[2][2][BB * HID];
__device__ __align__(16) __nv_bfloat16 d_hbf_lo[2][2][BB * HID];

// ---------------------------------------------------------------------------
// PTX helpers — base sm_100-safe (cp.async / ldmatrix / mma.sync)
// ---------------------------------------------------------------------------
__device__ __forceinline__ uint32_t smem_u32(const void* p) {
    uint32_t a;
    asm("{ .reg .u64 t; cvta.to.shared.u64 t, %1; cvt.u32.u64 %0, t; }" : "=r"(a) : "l"(p));
    return a;
}
__device__ __forceinline__ void cp_async16(uint32_t dst, const void* src) {
    asm volatile("cp.async.cg.shared.global [%0], [%1], 16;" :: "r"(dst), "l"(src));
}
#define CP_COMMIT() asm volatile("cp.async.commit_group;" ::: "memory")
#define CP_WAIT1()  asm volatile("cp.async.wait_group 1;" ::: "memory")
#define CP_WAIT0()  asm volatile("cp.async.wait_group 0;" ::: "memory")

__device__ __forceinline__ void ldm_x4(uint32_t* r, uint32_t a) {
    asm volatile("ldmatrix.sync.aligned.m8n8.x4.shared.b16 {%0,%1,%2,%3}, [%4];"
                 : "=r"(r[0]), "=r"(r[1]), "=r"(r[2]), "=r"(r[3]) : "r"(a));
}
// bf16 mma (lstm_rec path)
__device__ __forceinline__ void mma_bf16(float* d, const uint32_t* a, const uint32_t* b) {
    asm volatile("mma.sync.aligned.m16n8k16.row.col.f32.bf16.bf16.f32 "
                 "{%0,%1,%2,%3}, {%4,%5,%6,%7}, {%8,%9}, {%0,%1,%2,%3};"
                 : "+f"(d[0]), "+f"(d[1]), "+f"(d[2]), "+f"(d[3])
                 : "r"(a[0]), "r"(a[1]), "r"(a[2]), "r"(a[3]), "r"(b[0]), "r"(b[1]));
}
// tf32 mma m16n8k8
__device__ __forceinline__ void mma_tf32(float* d, const uint32_t* a, const uint32_t* b) {
    asm volatile("mma.sync.aligned.m16n8k8.row.col.f32.tf32.tf32.f32 "
                 "{%0,%1,%2,%3}, {%4,%5,%6,%7}, {%8,%9}, {%0,%1,%2,%3};"
                 : "+f"(d[0]), "+f"(d[1]), "+f"(d[2]), "+f"(d[3])
                 : "r"(a[0]), "r"(a[1]), "r"(a[2]), "r"(a[3]), "r"(b[0]), "r"(b[1]));
}
__device__ __forceinline__ uint32_t to_tf32(uint32_t x) {
    uint32_t y;
    asm("cvt.rna.tf32.f32 %0, %1;" : "=r"(y) : "r"(x));
    return y;
}

#define SWZ128(off) ((off) ^ (((off) >> 3) & 0x70))

// ---------------------------------------------------------------------------
// init: zero split-h buffers + barrier counters
// ---------------------------------------------------------------------------
__global__ void init_state() {
    int i = blockIdx.x * blockDim.x + threadIdx.x;
    if (i < 2 * 2 * BB * HID) {
        ((__nv_bfloat16*)d_hbf_hi)[i] = __float2bfloat16(0.f);
        ((__nv_bfloat16*)d_hbf_lo)[i] = __float2bfloat16(0.f);
    }
    if (i < 2) d_bar[i] = 0u;
}

// split helper for lstm_rec weight staging
__device__ __forceinline__ void split4(float4 v, __nv_bfloat162& H0, __nv_bfloat162& H1,
                                       __nv_bfloat162& L0, __nv_bfloat162& L1) {
    __nv_bfloat16 h0 = __float2bfloat16(v.x), h1 = __float2bfloat16(v.y);
    __nv_bfloat16 h2 = __float2bfloat16(v.z), h3 = __float2bfloat16(v.w);
    H0 = {h0, h1}; H1 = {h2, h3};
    L0 = {__float2bfloat16(v.x - __bfloat162float(h0)),
          __float2bfloat16(v.y - __bfloat162float(h1))};
    L1 = {__float2bfloat16(v.z - __bfloat162float(h2)),
          __float2bfloat16(v.w - __bfloat162float(h3))};
}

// ---------------------------------------------------------------------------
// transpose x (fp32): [b][512][1024] -> [b][1024][512]
// ---------------------------------------------------------------------------
__global__ void transpose_xf(const float* __restrict__ x, float* __restrict__ T)
{
    __shared__ float tile[32][33];
    const int b = blockIdx.z;
    const int d0 = blockIdx.x * 32, l0 = blockIdx.y * 32;
    const int tx = threadIdx.x, ty = threadIdx.y;
    const size_t si = (size_t)b * LL * HH;
    #pragma unroll
    for (int i = 0; i < 4; i++) {
        int l = ty + i * 8;
        tile[l][tx] = x[si + (size_t)(l0 + l) * HH + d0 + tx];
    }
    __syncthreads();
    const size_t so = (size_t)b * HH * LL;
    #pragma unroll
    for (int i = 0; i < 4; i++) {
        int d = ty + i * 8;
        T[so + (size_t)(d0 + d) * LL + l0 + tx] = tile[tx][d];
    }
}

// ---------------------------------------------------------------------------
// copy x into the second half of NX (float4)
// ---------------------------------------------------------------------------
__global__ void concat_copy(const float* __restrict__ x, float* __restrict__ nx)
{
    size_t i = (size_t)blockIdx.x * 256 + threadIdx.x;
    if (i >= (size_t)BB * LL * (HH / 4)) return;
    float4 v = ((const float4*)x)[i];
    size_t bl = i >> 8, d4 = i & 255;
    ((float4*)nx)[bl * (TWOH / 4) + (HH / 4) + d4] = v;
}

// ---------------------------------------------------------------------------
// TF32 single-pass tensor GEMM: C = A * B^T.
// Tile 128(M) x 64(N), 8 warps (4x2), warp tile 32x32. KC=64 floats stored
// as 2 chunk-columns of 128B rows (SW128). 2-stage cp.async, 2 CTAs/SM.
// EPI=0: fp32 C (batched, ldc/sC).  EPI=2: time-major gates + bias1+bias2.
// ---------------------------------------------------------------------------
#define KC 64
#define ACH 16384                 // one A chunk: 128 rows x 128B
#define BCH 8192                  // one B chunk: 64 rows x 128B
#define STAGE (2 * ACH + 2 * BCH) // 48KB
#define TF_DSMEM (1024 + 2 * STAGE)

template <int EPI>
__global__ void __launch_bounds__(256, 2) gemm_tf(
    const float* __restrict__ Af, const float* __restrict__ Bf,
    int K, int lda, int ldb, size_t sA, size_t sB,
    float* __restrict__ Cf, int ldc, size_t sC,
    const float* __restrict__ bias1, const float* __restrict__ bias2)
{
    extern __shared__ char dsm[];
    char* basep = (char*)(((uintptr_t)dsm + 1023) & ~(uintptr_t)1023);
    const uint32_t sbase = smem_u32(basep);

    const int tid = threadIdx.x;
    const int wid = tid >> 5, lane = tid & 31;
    const int warp_m = wid >> 1, warp_n = wid & 1;   // 4 x 2
    const int m0 = blockIdx.y * 128, n0 = blockIdx.x * 64;
    const int z = blockIdx.z;
    Af += (size_t)z * sA;
    Bf += (size_t)z * sB;

    float acc[2][4][4] = {};
    const int nchunk = K / KC;

    auto issue = [&](int chunk) {
        const uint32_t st = sbase + (chunk & 1) * STAGE;
        const int kc = chunk * KC;
        #pragma unroll
        for (int i = 0; i < 8; i++) {        // A: 2048 16B units
            int u = tid + i * 256;
            int r = u >> 4, cu = u & 15;
            int ch = cu >> 3, cw = cu & 7;
            uint32_t dst = st + ch * ACH + SWZ128((uint32_t)(r * 128 + cw * 16));
            cp_async16(dst, Af + (size_t)(m0 + r) * lda + kc + cu * 4);
        }
        #pragma unroll
        for (int i = 0; i < 4; i++) {        // B: 1024 16B units
            int u = tid + i * 256;
            int r = u >> 4, cu = u & 15;
            int ch = cu >> 3, cw = cu & 7;
            uint32_t dst = st + 2 * ACH + ch * BCH + SWZ128((uint32_t)(r * 128 + cw * 16));
            cp_async16(dst, Bf + (size_t)(n0 + r) * ldb + kc + cu * 4);
        }
    };

    issue(0); CP_COMMIT();

    for (int c = 0; c < nchunk; c++) {
        if (c + 1 < nchunk) issue(c + 1);
        CP_COMMIT();
        CP_WAIT1();
        __syncthreads();
        const uint32_t st = sbase + (c & 1) * STAGE;

        #pragma unroll
        for (int ks = 0; ks < 8; ks++) {     // 8 x k8 steps (2 chunks x 4)
            const uint32_t aBase = st + (ks >> 2) * ACH;
            const uint32_t bBase = st + 2 * ACH + (ks >> 2) * BCH;
            const int kb = (ks & 3) * 32;
            uint32_t af[2][4], bfr[4][2];
            #pragma unroll
            for (int mt = 0; mt < 2; mt++) {
                int row = warp_m * 32 + mt * 16 + (lane & 15);
                uint32_t off = SWZ128((uint32_t)(row * 128 + kb + ((lane >> 4) * 16)));
                ldm_x4(af[mt], aBase + off);
                #pragma unroll
                for (int q = 0; q < 4; q++) af[mt][q] = to_tf32(af[mt][q]);
            }
            #pragma unroll
            for (int ntp = 0; ntp < 2; ntp++) {
                int row = warp_n * 32 + ntp * 16 + ((lane >> 4) * 8) + (lane & 7);
                uint32_t off = SWZ128((uint32_t)(row * 128 + kb + (((lane >> 3) & 1) * 16)));
                uint32_t r4[4];
                ldm_x4(r4, bBase + off);
                bfr[2 * ntp][0]     = to_tf32(r4[0]);
                bfr[2 * ntp][1]     = to_tf32(r4[1]);
                bfr[2 * ntp + 1][0] = to_tf32(r4[2]);
                bfr[2 * ntp + 1][1] = to_tf32(r4[3]);
            }
            #pragma unroll
            for (int mt = 0; mt < 2; mt++)
                #pragma unroll
                for (int nt = 0; nt < 4; nt++)
                    mma_tf32(acc[mt][nt], af[mt], bfr[nt]);
        }
        __syncthreads();
    }

    // Epilogue (same D layout as m16n8k16)
    const int g = lane >> 2, tc = lane & 3;
    #pragma unroll
    for (int nt = 0; nt < 4; nt++) {
        int col = n0 + warp_n * 32 + nt * 8 + tc * 2;
        float b0v = 0.f, b1v = 0.f;
        if (EPI == 2) {
            b0v = bias1[col] + bias2[col];
            b1v = bias1[col + 1] + bias2[col + 1];
        }
        #pragma unroll
        for (int mt = 0; mt < 2; mt++) {
            #pragma unroll
            for (int half = 0; half < 2; half++) {
                int ml = warp_m * 32 + mt * 16 + g + half * 8;
                float v0 = acc[mt][nt][half * 2] + b0v;
                float v1 = acc[mt][nt][half * 2 + 1] + b1v;
                if (EPI == 0) {
                    *(float2*)(Cf + (size_t)z * sC + (size_t)(m0 + ml) * ldc + col)
                        = make_float2(v0, v1);
                } else {
                    int m = m0 + ml;
                    int t = m & 511, b = m >> 9;
                    *(float2*)(Cf + ((size_t)t * 32 + b) * 2048 + col)
                        = make_float2(v0, v1);
                }
            }
        }
    }
}

// ---------------------------------------------------------------------------
// Masked softmax over last axis (512), fp32 in-place
// ---------------------------------------------------------------------------
__global__ void __launch_bounds__(256) softmax512(float* __restrict__ S,
                                                  const float* __restrict__ mask)
{
    const int l = blockIdx.x, b = blockIdx.y;
    float* row = S + ((size_t)b * LL + l) * LL;
    const float* m = mask + (size_t)b * LL;
    const int tid = threadIdx.x;

    float m0 = m[tid], m1 = m[tid + 256];
    float v0 = (m0 > 0.5f) ? row[tid]       : -1e20f;
    float v1 = (m1 > 0.5f) ? row[tid + 256] : -1e20f;

    __shared__ float red[8];
    float mx = fmaxf(v0, v1);
    #pragma unroll
    for (int o = 16; o > 0; o >>= 1) mx = fmaxf(mx, __shfl_xor_sync(0xffffffffu, mx, o));
    if ((tid & 31) == 0) red[tid >> 5] = mx;
    __syncthreads();
    float bm = red[0];
    #pragma unroll
    for (int i = 1; i < 8; i++) bm = fmaxf(bm, red[i]);

    float e0 = expf(v0 - bm);
    float e1 = expf(v1 - bm);
    float sum = e0 + e1;
    #pragma unroll
    for (int o = 16; o > 0; o >>= 1) sum += __shfl_xor_sync(0xffffffffu, sum, o);
    __syncthreads();
    if ((tid & 31) == 0) red[tid >> 5] = sum;
    __syncthreads();
    float bs = 0.f;
    #pragma unroll
    for (int i = 0; i < 8; i++) bs += red[i];

    float inv = 1.0f / bs;
    row[tid]       = e0 * inv;
    row[tid + 256] = e1 * inv;
}

// ---------------------------------------------------------------------------
// Persistent bidirectional LSTM recurrence — TENSOR CORE bf16-split
// (verbatim from passing rounds 9-13)
// ---------------------------------------------------------------------------
__device__ __forceinline__ float sigm(float x) { return 1.0f / (1.0f + expf(-x)); }

#define LWH 0
#define LWL 32768
#define LHH 65536
#define LHL 98304
#define LSTM_DSMEM 132096

__global__ void __launch_bounds__(256, 1) lstm_rec(
    const float* __restrict__ Whf, const float* __restrict__ Whb,
    const int* __restrict__ x_len, float* __restrict__ out)
{
    extern __shared__ char lsm[];
    char* basep = (char*)(((uintptr_t)lsm + 1023) & ~(uintptr_t)1023);
    const uint32_t sbase = smem_u32(basep);

    __shared__ float gbuf[32][33];
    __shared__ float sG[32][36];
    __shared__ float cbuf[8][32];
    __shared__ float hown[8][32];
    __shared__ int s_len[32];

    const int tid = threadIdx.x;
    const int wid = tid >> 5, lane = tid & 31;
    const int warp_m = wid >> 2, warp_n = wid & 3;
    const int dir = blockIdx.x >> 6;
    const int u0 = (blockIdx.x & 63) * 8;
    const float* __restrict__ G = dir ? d_Gb : d_Gf;
    const float* __restrict__ W = dir ? Whb : Whf;

    if (tid < 32) s_len[tid] = x_len[tid];
    {
        int ul = tid & 7, b = tid >> 3;
        cbuf[ul][b] = 0.f; hown[ul][b] = 0.f;
    }

    {
        int lr = tid >> 3, kg = tid & 7;
        int r = (lr >> 3) * 512 + u0 + (lr & 7);
        const float4* wr = (const float4*)(W + (size_t)r * 512 + kg * 64);
        #pragma unroll
        for (int v = 0; v < 16; v++) {
            __nv_bfloat162 H0, H1, L0, L1;
            split4(wr[v], H0, H1, L0, L1);
            uint32_t off = kg * 4096 + SWZ128((uint32_t)(lr * 128 + v * 8));
            *(__nv_bfloat162*)(basep + LWH + off)     = H0;
            *(__nv_bfloat162*)(basep + LWH + off + 4) = H1;
            *(__nv_bfloat162*)(basep + LWL + off)     = L0;
            *(__nv_bfloat162*)(basep + LWL + off + 4) = L1;
        }
    }
    __syncthreads();

    const uint32_t aRowOff = (uint32_t)((warp_m * 16 + (lane & 15)) * 128 + (lane >> 4) * 16);
    const uint32_t bRowOff = (uint32_t)((warp_n * 8 + (lane & 7)) * 128 + ((lane >> 3) & 1) * 16);
    const uint32_t bTile = (lane < 16) ? (sbase + LWH) : (sbase + LWL);

    for (int s = 0; s < 512; s++) {
        const int t = dir ? (511 - s) : s;
        const int rb = s & 1, wb = rb ^ 1;
        const __nv_bfloat16* hgHi = &d_hbf_hi[dir][rb][0];
        const __nv_bfloat16* hgLo = &d_hbf_lo[dir][rb][0];

        #pragma unroll
        for (int i = 0; i < 8; i++) {
            int u = tid + i * 256;
            int b = u >> 6, ch = (u >> 3) & 7, cu = u & 7;
            uint32_t sw = ch * 4096 + SWZ128((uint32_t)(b * 128 + cu * 16));
            cp_async16(sbase + LHH + sw, hgHi + b * 512 + ch * 64 + cu * 8);
            cp_async16(sbase + LHL + sw, hgLo + b * 512 + ch * 64 + cu * 8);
        }
        CP_COMMIT();
        {
            int pair = tid >> 1, half = tid & 1;
            int b = pair >> 2, gate = pair & 3;
            const float* gsrc = G + ((size_t)t * 32 + b) * 2048 + gate * 512 + u0 + half * 4;
            cp_async16(smem_u32(&sG[b][gate * 8 + half * 4]), gsrc);
        }
        CP_COMMIT();
        CP_WAIT1();
        __syncthreads();

        float acc[4] = {0.f, 0.f, 0.f, 0.f};
        #pragma unroll 8
        for (int kst = 0; kst < 32; kst++) {
            uint32_t kc = (uint32_t)(kst >> 2) * 4096;
            uint32_t kb = (uint32_t)(kst & 3) * 32;
            uint32_t ao = kc + SWZ128(aRowOff + kb);
            uint32_t bo = kc + SWZ128(bRowOff + kb);
            uint32_t ah[4], al[4], bbx[4];
            ldm_x4(ah, sbase + LHH + ao);
            ldm_x4(al, sbase + LHL + ao);
            ldm_x4(bbx, bTile + bo);
            mma_bf16(acc, ah, bbx);
            mma_bf16(acc, ah, bbx + 2);
            mma_bf16(acc, al, bbx);
        }

        {
            int g = lane >> 2, tc = lane & 3;
            int n = warp_n * 8 + tc * 2, m = warp_m * 16 + g;
            gbuf[n][m]         = acc[0];
            gbuf[n + 1][m]     = acc[1];
            gbuf[n][m + 8]     = acc[2];
            gbuf[n + 1][m + 8] = acc[3];
        }
        CP_WAIT0();
        __syncthreads();

        {
            int b = tid >> 3, ul = tid & 7;
            float gi = gbuf[ul][b]      + sG[b][ul];
            float gf = gbuf[8 + ul][b]  + sG[b][8 + ul];
            float gg = gbuf[16 + ul][b] + sG[b][16 + ul];
            float go = gbuf[24 + ul][b] + sG[b][24 + ul];
            float c  = cbuf[ul][b];
            float nc = sigm(gf) * c + sigm(gi) * tanhf(gg);
            float nh = sigm(go) * tanhf(nc);
            bool valid = (t < s_len[b]);
            float hn = valid ? nh : hown[ul][b];
            float cn = valid ? nc : c;
            cbuf[ul][b] = cn;
            hown[ul][b] = hn;
            __nv_bfloat16 hhi = __float2bfloat16(hn);
            __nv_bfloat16 hlo = __float2bfloat16(hn - __bfloat162float(hhi));
            d_hbf_hi[dir][wb][b * 512 + u0 + ul] = hhi;
            d_hbf_lo[dir][wb][b * 512 + u0 + ul] = hlo;
            if (s == 511) out[(size_t)b * 1024 + dir * 512 + u0 + ul] = hn;
        }

        if (s == 511) break;

        __threadfence();
        __syncthreads();
        if (tid == 0) {
            atomicAdd(&d_bar[dir], 1u);
            const unsigned target = 64u * (unsigned)(s + 1);
            while (true) {
                unsigned v;
                asm volatile("ld.global.acquire.gpu.u32 %0, [%1];" : "=r"(v) : "l"(&d_bar[dir]));
                if (v >= target) break;
                __nanosleep(64);
            }
            __threadfence();
        }
        __syncthreads();
    }
}

// ---------------------------------------------------------------------------
// kernel_launch
// ---------------------------------------------------------------------------
extern "C" void kernel_launch(void* const* d_in, const int* in_sizes, int n_in,
                              void* d_out, int out_size)
{
    const float* x    = (const float*)d_in[0];
    const int*   xlen = (const int*)  d_in[1];
    const float* am   = (const float*)d_in[2];
    const float* Wif  = (const float*)d_in[3];
    const float* Whf  = (const float*)d_in[4];
    const float* bif  = (const float*)d_in[5];
    const float* bhf  = (const float*)d_in[6];
    const float* Wib  = (const float*)d_in[7];
    const float* Whb  = (const float*)d_in[8];
    const float* bib  = (const float*)d_in[9];
    const float* bhb  = (const float*)d_in[10];
    float* out = (float*)d_out;

    void *pS, *pxT, *pNX, *pGf, *pGb;
    cudaGetSymbolAddress(&pS,  d_S);
    cudaGetSymbolAddress(&pxT, d_xT);
    cudaGetSymbolAddress(&pNX, d_NX);
    cudaGetSymbolAddress(&pGf, d_Gf);
    cudaGetSymbolAddress(&pGb, d_Gb);
    float* S  = (float*)pS;
    float* xT = (float*)pxT;
    float* NX = (float*)pNX;
    float* Gf = (float*)pGf;
    float* Gb = (float*)pGb;

    cudaFuncSetAttribute(lstm_rec, cudaFuncAttributeMaxDynamicSharedMemorySize, LSTM_DSMEM);
    cudaFuncSetAttribute(gemm_tf<0>, cudaFuncAttributeMaxDynamicSharedMemorySize, TF_DSMEM);
    cudaFuncSetAttribute(gemm_tf<2>, cudaFuncAttributeMaxDynamicSharedMemorySize, TF_DSMEM);

    init_state<<<256, 256>>>();

    // x^T per batch (fp32)
    transpose_xf<<<dim3(HH / 32, LL / 32, BB), dim3(32, 8)>>>(x, xT);

    // NX second half = x
    concat_copy<<<(BB * LL * (HH / 4) + 255) / 256, 256>>>(x, NX);

    // scores: S[b] = x_b * x_b^T  (M=512, N=512, K=1024)
    gemm_tf<0><<<dim3(LL / 64, LL / 128, BB), 256, TF_DSMEM>>>(
        x, x, HH, HH, HH, (size_t)LL * HH, (size_t)LL * HH,
        S, LL, (size_t)LL * LL, nullptr, nullptr);

    softmax512<<<dim3(LL, BB), 256>>>(S, am);

    // att @ x -> NX[:, :, 0:1024]  (M=512, N=1024, K=512; B = x^T rows)
    gemm_tf<0><<<dim3(HH / 64, LL / 128, BB), 256, TF_DSMEM>>>(
        S, xT, LL, LL, LL, (size_t)LL * LL, (size_t)HH * LL,
        NX, TWOH, (size_t)LL * TWOH, nullptr, nullptr);

    // gates: G_d = NX @ W_ih_d^T + bias  (M=16384, N=2048, K=2048), time-major
    gemm_tf<2><<<dim3(G4 / 64, (BB * LL) / 128, 1), 256, TF_DSMEM>>>(
        NX, Wif, TWOH, TWOH, TWOH, 0, 0,
        Gf, 0, 0, bif, bhf);
    gemm_tf<2><<<dim3(G4 / 64, (BB * LL) / 128, 1), 256, TF_DSMEM>>>(
        NX, Wib, TWOH, TWOH, TWOH, 0, 0,
        Gb, 0, 0, bib, bhb);

    // Persistent bidirectional recurrence (bf16-split tensor path, unchanged)
    lstm_rec<<<128, 256, LSTM_DSMEM>>>(Whf, Whb, xlen, out);
}

// round 15
// speedup vs baseline: 1.1143x; 1.0682x over previous
#include <cuda_runtime.h>
#include <cuda_bf16.h>
#include <cstdint>
#include <cstddef>

// Problem constants
#define BB 32
#define LL 512
#define HH 1024
#define HID 512
#define G4 2048   // 4*HID
#define TWOH 2048 // 2*H

// ---------------------------------------------------------------------------
// Scratch (static __device__ arrays)
// ---------------------------------------------------------------------------
__device__ __align__(16) float d_S[(size_t)BB * LL * LL];        // scores/att (tf32-rounded after softmax)
__device__ __align__(16) float d_xr[(size_t)BB * LL * HH];       // tf32-rounded x
__device__ __align__(16) float d_xT[(size_t)BB * HH * LL];       // tf32-rounded x^T
__device__ __align__(16) float d_NX[(size_t)BB * LL * TWOH];     // tf32-rounded [att@x, x]
__device__ __align__(16) float d_Wr[2][(size_t)G4 * TWOH];       // tf32-rounded W_ih
__device__ __align__(16) float d_Gf[(size_t)LL * BB * G4];       // gates fwd [t][b][4H] fp32
__device__ __align__(16) float d_Gb[(size_t)LL * BB * G4];
__device__ unsigned d_bar[2];
// h ping-pong in split bf16 (lstm_rec path, unchanged)
__device__ __align__(16) __nv_bfloat16 d_hbf_hi[2][2][BB * HID];
__device__ __align__(16) __nv_bfloat16 d_hbf_lo[2][2][BB * HID];

// ---------------------------------------------------------------------------
// PTX helpers — base sm_100-safe (cp.async / ldmatrix / mma.sync)
// ---------------------------------------------------------------------------
__device__ __forceinline__ uint32_t smem_u32(const void* p) {
    uint32_t a;
    asm("{ .reg .u64 t; cvta.to.shared.u64 t, %1; cvt.u32.u64 %0, t; }" : "=r"(a) : "l"(p));
    return a;
}
__device__ __forceinline__ void cp_async16(uint32_t dst, const void* src) {
    asm volatile("cp.async.cg.shared.global [%0], [%1], 16;" :: "r"(dst), "l"(src));
}
#define CP_COMMIT() asm volatile("cp.async.commit_group;" ::: "memory")
#define CP_WAIT1()  asm volatile("cp.async.wait_group 1;" ::: "memory")
#define CP_WAIT0()  asm volatile("cp.async.wait_group 0;" ::: "memory")

__device__ __forceinline__ void ldm_x4(uint32_t* r, uint32_t a) {
    asm volatile("ldmatrix.sync.aligned.m8n8.x4.shared.b16 {%0,%1,%2,%3}, [%4];"
                 : "=r"(r[0]), "=r"(r[1]), "=r"(r[2]), "=r"(r[3]) : "r"(a));
}
__device__ __forceinline__ void mma_bf16(float* d, const uint32_t* a, const uint32_t* b) {
    asm volatile("mma.sync.aligned.m16n8k16.row.col.f32.bf16.bf16.f32 "
                 "{%0,%1,%2,%3}, {%4,%5,%6,%7}, {%8,%9}, {%0,%1,%2,%3};"
                 : "+f"(d[0]), "+f"(d[1]), "+f"(d[2]), "+f"(d[3])
                 : "r"(a[0]), "r"(a[1]), "r"(a[2]), "r"(a[3]), "r"(b[0]), "r"(b[1]));
}
__device__ __forceinline__ void mma_tf32(float* d, const uint32_t* a, const uint32_t* b) {
    asm volatile("mma.sync.aligned.m16n8k8.row.col.f32.tf32.tf32.f32 "
                 "{%0,%1,%2,%3}, {%4,%5,%6,%7}, {%8,%9}, {%0,%1,%2,%3};"
                 : "+f"(d[0]), "+f"(d[1]), "+f"(d[2]), "+f"(d[3])
                 : "r"(a[0]), "r"(a[1]), "r"(a[2]), "r"(a[3]), "r"(b[0]), "r"(b[1]));
}
__device__ __forceinline__ float tf32r(float x) {
    uint32_t y;
    asm("cvt.rna.tf32.f32 %0, %1;" : "=r"(y) : "f"(x));
    return __uint_as_float(y);
}

#define SWZ128(off) ((off) ^ (((off) >> 3) & 0x70))

// ---------------------------------------------------------------------------
// init: zero split-h buffers + barrier counters
// ---------------------------------------------------------------------------
__global__ void init_state() {
    int i = blockIdx.x * blockDim.x + threadIdx.x;
    if (i < 2 * 2 * BB * HID) {
        ((__nv_bfloat16*)d_hbf_hi)[i] = __float2bfloat16(0.f);
        ((__nv_bfloat16*)d_hbf_lo)[i] = __float2bfloat16(0.f);
    }
    if (i < 2) d_bar[i] = 0u;
}

// split helper for lstm_rec weight staging
__device__ __forceinline__ void split4(float4 v, __nv_bfloat162& H0, __nv_bfloat162& H1,
                                       __nv_bfloat162& L0, __nv_bfloat162& L1) {
    __nv_bfloat16 h0 = __float2bfloat16(v.x), h1 = __float2bfloat16(v.y);
    __nv_bfloat16 h2 = __float2bfloat16(v.z), h3 = __float2bfloat16(v.w);
    H0 = {h0, h1}; H1 = {h2, h3};
    L0 = {__float2bfloat16(v.x - __bfloat162float(h0)),
          __float2bfloat16(v.y - __bfloat162float(h1))};
    L1 = {__float2bfloat16(v.z - __bfloat162float(h2)),
          __float2bfloat16(v.w - __bfloat162float(h3))};
}

// ---------------------------------------------------------------------------
// elementwise tf32 rounding: dst[i] = tf32(src[i])
// ---------------------------------------------------------------------------
__global__ void __launch_bounds__(256) round_tf32(
    const float* __restrict__ src, float* __restrict__ dst, size_t n4)
{
    size_t i = (size_t)blockIdx.x * 256 + threadIdx.x;
    if (i >= n4) return;
    float4 v = ((const float4*)src)[i];
    v.x = tf32r(v.x); v.y = tf32r(v.y); v.z = tf32r(v.z); v.w = tf32r(v.w);
    ((float4*)dst)[i] = v;
}

// ---------------------------------------------------------------------------
// transpose x with tf32 rounding: [b][512][1024] -> [b][1024][512]
// ---------------------------------------------------------------------------
__global__ void transpose_xf(const float* __restrict__ x, float* __restrict__ T)
{
    __shared__ float tile[32][33];
    const int b = blockIdx.z;
    const int d0 = blockIdx.x * 32, l0 = blockIdx.y * 32;
    const int tx = threadIdx.x, ty = threadIdx.y;
    const size_t si = (size_t)b * LL * HH;
    #pragma unroll
    for (int i = 0; i < 4; i++) {
        int l = ty + i * 8;
        tile[l][tx] = x[si + (size_t)(l0 + l) * HH + d0 + tx];
    }
    __syncthreads();
    const size_t so = (size_t)b * HH * LL;
    #pragma unroll
    for (int i = 0; i < 4; i++) {
        int d = ty + i * 8;
        T[so + (size_t)(d0 + d) * LL + l0 + tx] = tf32r(tile[tx][d]);
    }
}

// ---------------------------------------------------------------------------
// copy x into the second half of NX, tf32-rounded
// ---------------------------------------------------------------------------
__global__ void concat_copy(const float* __restrict__ x, float* __restrict__ nx)
{
    size_t i = (size_t)blockIdx.x * 256 + threadIdx.x;
    if (i >= (size_t)BB * LL * (HH / 4)) return;
    float4 v = ((const float4*)x)[i];
    v.x = tf32r(v.x); v.y = tf32r(v.y); v.z = tf32r(v.z); v.w = tf32r(v.w);
    size_t bl = i >> 8, d4 = i & 255;
    ((float4*)nx)[bl * (TWOH / 4) + (HH / 4) + d4] = v;
}

// ---------------------------------------------------------------------------
// TF32 single-pass tensor GEMM (operands pre-rounded; NO in-loop cvt).
// Tile 128(M) x 64(N), 8 warps (4x2), warp tile 32x32. KC=64 floats as
// 2 chunk-columns of 128B rows (SW128). 2-stage cp.async, 2 CTAs/SM.
// EPI=0: fp32 C batched. EPI=1: tf32-rounded fp32 C batched (NX).
// EPI=2: time-major gates + bias1+bias2 (fp32).
// ---------------------------------------------------------------------------
#define KC 64
#define ACH 16384
#define BCH 8192
#define STAGE (2 * ACH + 2 * BCH)
#define TF_DSMEM (1024 + 2 * STAGE)

template <int EPI>
__global__ void __launch_bounds__(256, 2) gemm_tf(
    const float* __restrict__ Af, const float* __restrict__ Bf,
    int K, int lda, int ldb, size_t sA, size_t sB,
    float* __restrict__ Cf, int ldc, size_t sC,
    const float* __restrict__ bias1, const float* __restrict__ bias2)
{
    extern __shared__ char dsm[];
    char* basep = (char*)(((uintptr_t)dsm + 1023) & ~(uintptr_t)1023);
    const uint32_t sbase = smem_u32(basep);

    const int tid = threadIdx.x;
    const int wid = tid >> 5, lane = tid & 31;
    const int warp_m = wid >> 1, warp_n = wid & 1;
    const int m0 = blockIdx.y * 128, n0 = blockIdx.x * 64;
    const int z = blockIdx.z;
    Af += (size_t)z * sA;
    Bf += (size_t)z * sB;

    float acc[2][4][4] = {};
    const int nchunk = K / KC;

    auto issue = [&](int chunk) {
        const uint32_t st = sbase + (chunk & 1) * STAGE;
        const int kc = chunk * KC;
        #pragma unroll
        for (int i = 0; i < 8; i++) {
            int u = tid + i * 256;
            int r = u >> 4, cu = u & 15;
            int ch = cu >> 3, cw = cu & 7;
            uint32_t dst = st + ch * ACH + SWZ128((uint32_t)(r * 128 + cw * 16));
            cp_async16(dst, Af + (size_t)(m0 + r) * lda + kc + cu * 4);
        }
        #pragma unroll
        for (int i = 0; i < 4; i++) {
            int u = tid + i * 256;
            int r = u >> 4, cu = u & 15;
            int ch = cu >> 3, cw = cu & 7;
            uint32_t dst = st + 2 * ACH + ch * BCH + SWZ128((uint32_t)(r * 128 + cw * 16));
            cp_async16(dst, Bf + (size_t)(n0 + r) * ldb + kc + cu * 4);
        }
    };

    issue(0); CP_COMMIT();

    for (int c = 0; c < nchunk; c++) {
        if (c + 1 < nchunk) issue(c + 1);
        CP_COMMIT();
        CP_WAIT1();
        __syncthreads();
        const uint32_t st = sbase + (c & 1) * STAGE;

        #pragma unroll
        for (int ks = 0; ks < 8; ks++) {
            const uint32_t aBase = st + (ks >> 2) * ACH;
            const uint32_t bBase = st + 2 * ACH + (ks >> 2) * BCH;
            const int kb = (ks & 3) * 32;
            uint32_t af[2][4], bfr[4][2];
            #pragma unroll
            for (int mt = 0; mt < 2; mt++) {
                int row = warp_m * 32 + mt * 16 + (lane & 15);
                uint32_t off = SWZ128((uint32_t)(row * 128 + kb + ((lane >> 4) * 16)));
                ldm_x4(af[mt], aBase + off);
            }
            #pragma unroll
            for (int ntp = 0; ntp < 2; ntp++) {
                int row = warp_n * 32 + ntp * 16 + ((lane >> 4) * 8) + (lane & 7);
                uint32_t off = SWZ128((uint32_t)(row * 128 + kb + (((lane >> 3) & 1) * 16)));
                uint32_t r4[4];
                ldm_x4(r4, bBase + off);
                bfr[2 * ntp][0]     = r4[0];
                bfr[2 * ntp][1]     = r4[1];
                bfr[2 * ntp + 1][0] = r4[2];
                bfr[2 * ntp + 1][1] = r4[3];
            }
            #pragma unroll
            for (int mt = 0; mt < 2; mt++)
                #pragma unroll
                for (int nt = 0; nt < 4; nt++)
                    mma_tf32(acc[mt][nt], af[mt], bfr[nt]);
        }
        __syncthreads();
    }

    // Epilogue
    const int g = lane >> 2, tc = lane & 3;
    #pragma unroll
    for (int nt = 0; nt < 4; nt++) {
        int col = n0 + warp_n * 32 + nt * 8 + tc * 2;
        float b0v = 0.f, b1v = 0.f;
        if (EPI == 2) {
            b0v = bias1[col] + bias2[col];
            b1v = bias1[col + 1] + bias2[col + 1];
        }
        #pragma unroll
        for (int mt = 0; mt < 2; mt++) {
            #pragma unroll
            for (int half = 0; half < 2; half++) {
                int ml = warp_m * 32 + mt * 16 + g + half * 8;
                float v0 = acc[mt][nt][half * 2] + b0v;
                float v1 = acc[mt][nt][half * 2 + 1] + b1v;
                if (EPI == 0) {
                    *(float2*)(Cf + (size_t)z * sC + (size_t)(m0 + ml) * ldc + col)
                        = make_float2(v0, v1);
                } else if (EPI == 1) {
                    *(float2*)(Cf + (size_t)z * sC + (size_t)(m0 + ml) * ldc + col)
                        = make_float2(tf32r(v0), tf32r(v1));
                } else {
                    int m = m0 + ml;
                    int t = m & 511, b = m >> 9;
                    *(float2*)(Cf + ((size_t)t * 32 + b) * 2048 + col)
                        = make_float2(v0, v1);
                }
            }
        }
    }
}

// ---------------------------------------------------------------------------
// Masked softmax over last axis (512), tf32-rounded output in place
// ---------------------------------------------------------------------------
__global__ void __launch_bounds__(256) softmax512(float* __restrict__ S,
                                                  const float* __restrict__ mask)
{
    const int l = blockIdx.x, b = blockIdx.y;
    float* row = S + ((size_t)b * LL + l) * LL;
    const float* m = mask + (size_t)b * LL;
    const int tid = threadIdx.x;

    float m0 = m[tid], m1 = m[tid + 256];
    float v0 = (m0 > 0.5f) ? row[tid]       : -1e20f;
    float v1 = (m1 > 0.5f) ? row[tid + 256] : -1e20f;

    __shared__ float red[8];
    float mx = fmaxf(v0, v1);
    #pragma unroll
    for (int o = 16; o > 0; o >>= 1) mx = fmaxf(mx, __shfl_xor_sync(0xffffffffu, mx, o));
    if ((tid & 31) == 0) red[tid >> 5] = mx;
    __syncthreads();
    float bm = red[0];
    #pragma unroll
    for (int i = 1; i < 8; i++) bm = fmaxf(bm, red[i]);

    float e0 = expf(v0 - bm);
    float e1 = expf(v1 - bm);
    float sum = e0 + e1;
    #pragma unroll
    for (int o = 16; o > 0; o >>= 1) sum += __shfl_xor_sync(0xffffffffu, sum, o);
    __syncthreads();
    if ((tid & 31) == 0) red[tid >> 5] = sum;
    __syncthreads();
    float bs = 0.f;
    #pragma unroll
    for (int i = 0; i < 8; i++) bs += red[i];

    float inv = 1.0f / bs;
    row[tid]       = tf32r(e0 * inv);
    row[tid + 256] = tf32r(e1 * inv);
}

// ---------------------------------------------------------------------------
// Persistent bidirectional LSTM recurrence — TENSOR CORE bf16-split
// (verbatim from passing rounds 9-14)
// ---------------------------------------------------------------------------
__device__ __forceinline__ float sigm(float x) { return 1.0f / (1.0f + expf(-x)); }

#define LWH 0
#define LWL 32768
#define LHH 65536
#define LHL 98304
#define LSTM_DSMEM 132096

__global__ void __launch_bounds__(256, 1) lstm_rec(
    const float* __restrict__ Whf, const float* __restrict__ Whb,
    const int* __restrict__ x_len, float* __restrict__ out)
{
    extern __shared__ char lsm[];
    char* basep = (char*)(((uintptr_t)lsm + 1023) & ~(uintptr_t)1023);
    const uint32_t sbase = smem_u32(basep);

    __shared__ float gbuf[32][33];
    __shared__ float sG[32][36];
    __shared__ float cbuf[8][32];
    __shared__ float hown[8][32];
    __shared__ int s_len[32];

    const int tid = threadIdx.x;
    const int wid = tid >> 5, lane = tid & 31;
    const int warp_m = wid >> 2, warp_n = wid & 3;
    const int dir = blockIdx.x >> 6;
    const int u0 = (blockIdx.x & 63) * 8;
    const float* __restrict__ G = dir ? d_Gb : d_Gf;
    const float* __restrict__ W = dir ? Whb : Whf;

    if (tid < 32) s_len[tid] = x_len[tid];
    {
        int ul = tid & 7, b = tid >> 3;
        cbuf[ul][b] = 0.f; hown[ul][b] = 0.f;
    }

    {
        int lr = tid >> 3, kg = tid & 7;
        int r = (lr >> 3) * 512 + u0 + (lr & 7);
        const float4* wr = (const float4*)(W + (size_t)r * 512 + kg * 64);
        #pragma unroll
        for (int v = 0; v < 16; v++) {
            __nv_bfloat162 H0, H1, L0, L1;
            split4(wr[v], H0, H1, L0, L1);
            uint32_t off = kg * 4096 + SWZ128((uint32_t)(lr * 128 + v * 8));
            *(__nv_bfloat162*)(basep + LWH + off)     = H0;
            *(__nv_bfloat162*)(basep + LWH + off + 4) = H1;
            *(__nv_bfloat162*)(basep + LWL + off)     = L0;
            *(__nv_bfloat162*)(basep + LWL + off + 4) = L1;
        }
    }
    __syncthreads();

    const uint32_t aRowOff = (uint32_t)((warp_m * 16 + (lane & 15)) * 128 + (lane >> 4) * 16);
    const uint32_t bRowOff = (uint32_t)((warp_n * 8 + (lane & 7)) * 128 + ((lane >> 3) & 1) * 16);
    const uint32_t bTile = (lane < 16) ? (sbase + LWH) : (sbase + LWL);

    for (int s = 0; s < 512; s++) {
        const int t = dir ? (511 - s) : s;
        const int rb = s & 1, wb = rb ^ 1;
        const __nv_bfloat16* hgHi = &d_hbf_hi[dir][rb][0];
        const __nv_bfloat16* hgLo = &d_hbf_lo[dir][rb][0];

        #pragma unroll
        for (int i = 0; i < 8; i++) {
            int u = tid + i * 256;
            int b = u >> 6, ch = (u >> 3) & 7, cu = u & 7;
            uint32_t sw = ch * 4096 + SWZ128((uint32_t)(b * 128 + cu * 16));
            cp_async16(sbase + LHH + sw, hgHi + b * 512 + ch * 64 + cu * 8);
            cp_async16(sbase + LHL + sw, hgLo + b * 512 + ch * 64 + cu * 8);
        }
        CP_COMMIT();
        {
            int pair = tid >> 1, half = tid & 1;
            int b = pair >> 2, gate = pair & 3;
            const float* gsrc = G + ((size_t)t * 32 + b) * 2048 + gate * 512 + u0 + half * 4;
            cp_async16(smem_u32(&sG[b][gate * 8 + half * 4]), gsrc);
        }
        CP_COMMIT();
        CP_WAIT1();
        __syncthreads();

        float acc[4] = {0.f, 0.f, 0.f, 0.f};
        #pragma unroll 8
        for (int kst = 0; kst < 32; kst++) {
            uint32_t kc = (uint32_t)(kst >> 2) * 4096;
            uint32_t kb = (uint32_t)(kst & 3) * 32;
            uint32_t ao = kc + SWZ128(aRowOff + kb);
            uint32_t bo = kc + SWZ128(bRowOff + kb);
            uint32_t ah[4], al[4], bbx[4];
            ldm_x4(ah, sbase + LHH + ao);
            ldm_x4(al, sbase + LHL + ao);
            ldm_x4(bbx, bTile + bo);
            mma_bf16(acc, ah, bbx);
            mma_bf16(acc, ah, bbx + 2);
            mma_bf16(acc, al, bbx);
        }

        {
            int g = lane >> 2, tc = lane & 3;
            int n = warp_n * 8 + tc * 2, m = warp_m * 16 + g;
            gbuf[n][m]         = acc[0];
            gbuf[n + 1][m]     = acc[1];
            gbuf[n][m + 8]     = acc[2];
            gbuf[n + 1][m + 8] = acc[3];
        }
        CP_WAIT0();
        __syncthreads();

        {
            int b = tid >> 3, ul = tid & 7;
            float gi = gbuf[ul][b]      + sG[b][ul];
            float gf = gbuf[8 + ul][b]  + sG[b][8 + ul];
            float gg = gbuf[16 + ul][b] + sG[b][16 + ul];
            float go = gbuf[24 + ul][b] + sG[b][24 + ul];
            float c  = cbuf[ul][b];
            float nc = sigm(gf) * c + sigm(gi) * tanhf(gg);
            float nh = sigm(go) * tanhf(nc);
            bool valid = (t < s_len[b]);
            float hn = valid ? nh : hown[ul][b];
            float cn = valid ? nc : c;
            cbuf[ul][b] = cn;
            hown[ul][b] = hn;
            __nv_bfloat16 hhi = __float2bfloat16(hn);
            __nv_bfloat16 hlo = __float2bfloat16(hn - __bfloat162float(hhi));
            d_hbf_hi[dir][wb][b * 512 + u0 + ul] = hhi;
            d_hbf_lo[dir][wb][b * 512 + u0 + ul] = hlo;
            if (s == 511) out[(size_t)b * 1024 + dir * 512 + u0 + ul] = hn;
        }

        if (s == 511) break;

        __threadfence();
        __syncthreads();
        if (tid == 0) {
            atomicAdd(&d_bar[dir], 1u);
            const unsigned target = 64u * (unsigned)(s + 1);
            while (true) {
                unsigned v;
                asm volatile("ld.global.acquire.gpu.u32 %0, [%1];" : "=r"(v) : "l"(&d_bar[dir]));
                if (v >= target) break;
                __nanosleep(64);
            }
            __threadfence();
        }
        __syncthreads();
    }
}

// ---------------------------------------------------------------------------
// kernel_launch
// ---------------------------------------------------------------------------
extern "C" void kernel_launch(void* const* d_in, const int* in_sizes, int n_in,
                              void* d_out, int out_size)
{
    const float* x    = (const float*)d_in[0];
    const int*   xlen = (const int*)  d_in[1];
    const float* am   = (const float*)d_in[2];
    const float* Wif  = (const float*)d_in[3];
    const float* Whf  = (const float*)d_in[4];
    const float* bif  = (const float*)d_in[5];
    const float* bhf  = (const float*)d_in[6];
    const float* Wib  = (const float*)d_in[7];
    const float* Whb  = (const float*)d_in[8];
    const float* bib  = (const float*)d_in[9];
    const float* bhb  = (const float*)d_in[10];
    float* out = (float*)d_out;

    void *pS, *pxr, *pxT, *pNX, *pWr, *pGf, *pGb;
    cudaGetSymbolAddress(&pS,  d_S);
    cudaGetSymbolAddress(&pxr, d_xr);
    cudaGetSymbolAddress(&pxT, d_xT);
    cudaGetSymbolAddress(&pNX, d_NX);
    cudaGetSymbolAddress(&pWr, d_Wr);
    cudaGetSymbolAddress(&pGf, d_Gf);
    cudaGetSymbolAddress(&pGb, d_Gb);
    float* S  = (float*)pS;
    float* xr = (float*)pxr;
    float* xT = (float*)pxT;
    float* NX = (float*)pNX;
    float* Wr0 = (float*)pWr;
    float* Wr1 = Wr0 + (size_t)G4 * TWOH;
    float* Gf = (float*)pGf;
    float* Gb = (float*)pGb;

    cudaFuncSetAttribute(lstm_rec, cudaFuncAttributeMaxDynamicSharedMemorySize, LSTM_DSMEM);
    cudaFuncSetAttribute(gemm_tf<0>, cudaFuncAttributeMaxDynamicSharedMemorySize, TF_DSMEM);
    cudaFuncSetAttribute(gemm_tf<1>, cudaFuncAttributeMaxDynamicSharedMemorySize, TF_DSMEM);
    cudaFuncSetAttribute(gemm_tf<2>, cudaFuncAttributeMaxDynamicSharedMemorySize, TF_DSMEM);

    init_state<<<256, 256>>>();

    // tf32 pre-rounding of all GEMM operands
    {
        size_t n4 = (size_t)BB * LL * HH / 4;
        round_tf32<<<(unsigned)((n4 + 255) / 256), 256>>>(x, xr, n4);
        size_t w4 = (size_t)G4 * TWOH / 4;
        round_tf32<<<(unsigned)((w4 + 255) / 256), 256>>>(Wif, Wr0, w4);
        round_tf32<<<(unsigned)((w4 + 255) / 256), 256>>>(Wib, Wr1, w4);
    }
    transpose_xf<<<dim3(HH / 32, LL / 32, BB), dim3(32, 8)>>>(x, xT);
    concat_copy<<<(BB * LL * (HH / 4) + 255) / 256, 256>>>(x, NX);

    // scores: S[b] = xr_b * xr_b^T  (M=512, N=512, K=1024)
    gemm_tf<0><<<dim3(LL / 64, LL / 128, BB), 256, TF_DSMEM>>>(
        xr, xr, HH, HH, HH, (size_t)LL * HH, (size_t)LL * HH,
        S, LL, (size_t)LL * LL, nullptr, nullptr);

    softmax512<<<dim3(LL, BB), 256>>>(S, am);

    // att @ x -> NX[:, :, 0:1024], tf32-rounded (M=512, N=1024, K=512)
    gemm_tf<1><<<dim3(HH / 64, LL / 128, BB), 256, TF_DSMEM>>>(
        S, xT, LL, LL, LL, (size_t)LL * LL, (size_t)HH * LL,
        NX, TWOH, (size_t)LL * TWOH, nullptr, nullptr);

    // gates: G_d = NX @ Wr_d^T + bias  (M=16384, N=2048, K=2048), time-major
    gemm_tf<2><<<dim3(G4 / 64, (BB * LL) / 128, 1), 256, TF_DSMEM>>>(
        NX, Wr0, TWOH, TWOH, TWOH, 0, 0,
        Gf, 0, 0, bif, bhf);
    gemm_tf<2><<<dim3(G4 / 64, (BB * LL) / 128, 1), 256, TF_DSMEM>>>(
        NX, Wr1, TWOH, TWOH, TWOH, 0, 0,
        Gb, 0, 0, bib, bhb);

    // Persistent bidirectional recurrence (bf16-split tensor path, unchanged)
    lstm_rec<<<128, 256, LSTM_DSMEM>>>(Whf, Whb, xlen, out);
}